// round 13
// baseline (speedup 1.0000x reference)
#include <cuda_runtime.h>

#define B_  256
#define T_  2048
#define H_  64
#define O_  2
#define NROWS (B_ * T_)
#define PF  4   // step unroll (T_ % PF == 0)

// Scratch (device global — no allocation allowed in kernel_launch)
__device__ float g_bufB[NROWS * H_];

// ---------- packed f32x2 helpers (sm_103a FFMA2 path) ----------
static __device__ __forceinline__ unsigned long long pack2(float lo, float hi) {
    unsigned long long r;
    asm("mov.b64 %0, {%1, %2};" : "=l"(r) : "f"(lo), "f"(hi));
    return r;
}
static __device__ __forceinline__ void unpack2(unsigned long long v, float& a, float& b) {
    asm("mov.b64 {%0, %1}, %2;" : "=f"(a), "=f"(b) : "l"(v));
}
static __device__ __forceinline__ unsigned long long fma2(unsigned long long a,
                                                          unsigned long long b,
                                                          unsigned long long c) {
    unsigned long long d;
    asm("fma.rn.f32x2 %0, %1, %2, %3;" : "=l"(d) : "l"(a), "l"(b), "l"(c));
    return d;
}
static __device__ __forceinline__ unsigned long long add2(unsigned long long a,
                                                          unsigned long long b) {
    unsigned long long d;
    asm("add.rn.f32x2 %0, %1, %2;" : "=l"(d) : "l"(a), "l"(b));
    return d;
}

// Fast tanh, rel err ~1e-7, saturates correctly.
static __device__ __forceinline__ float fast_tanh(float x) {
    float e = __expf(2.0f * x);
    return 1.0f - __fdividef(2.0f, e + 1.0f);
}

#define NAMED_BAR(id, cnt) asm volatile("bar.sync %0, %1;" :: "r"(id), "r"(cnt) : "memory")

// ============================================================================
// fused_scan, warp-specialized:
//  CONSUMER warps (4/batch, R12 math): at step i
//    h0_i     = tanh(xin0_i + W_hh0 h0_{i-1})
//    h1_{i-1} = tanh(W_ih1 h0_{i-1} + b1rnn + W_hh1 h1_{i-2})
//    z_{i-2}  = relu(W1 h1_{i-2} + b1mlp)
//    xin0_i read from smem ring (filled by producers).
//  PRODUCER warps (2/batch): at interval n
//    STS raw x_{n+2} (reg, LDG'd at n-2); LDG x_{n+4};
//    xin0_{n+1} = W_ih0 x_{n+1} + b_ih0 + b_hh0 -> ring slot (n+1)&7.
//  All handoffs ordered by the per-batch named barrier (count 192 = 6 warps).
//  Producer issue (~120cyc) fills the consumers' latency tail -> the input
//  GEMM rides for free; xin never touches DRAM.
//  Block = 384 thr = 2 batches x (4 consumer + 2 producer) warps.
// ============================================================================
__global__ void __launch_bounds__(384, 1) fused_scan_kernel(
    const float* __restrict__ x,
    const float* __restrict__ Wih0,
    const float* __restrict__ b_ih0, const float* __restrict__ b_hh0,
    const float* __restrict__ Whh0, const float* __restrict__ Wih1,
    const float* __restrict__ Whh1,
    const float* __restrict__ b_ih1, const float* __restrict__ b_hh1,
    const float* __restrict__ W1,   const float* __restrict__ b1,
    float* __restrict__ zout)
{
    __shared__ __align__(16) float h0sm[2][2][64];
    __shared__ __align__(16) float h1sm[2][2][64];
    __shared__ __align__(16) float xir[2][8][64];              // xin0 ring
    __shared__ __align__(16) unsigned long long xraw[2][8][32]; // raw x ring (u64 pairs)

    const int tid = threadIdx.x;
    const int l   = tid & 31;
    const int wid = tid >> 5;

    if (wid < 8) {
        // ======================= CONSUMER =======================
        const int bl    = wid >> 2;            // batch slot (0..1)
        const int wq    = wid & 3;             // warp-in-batch
        const int j     = wq * 16 + (l & 15);  // owned output
        const int kh    = l >> 4;              // K-half
        const bool lead = (l < 16);
        const long b    = blockIdx.x * 2 + bl;
        const int barid = bl + 1;

        const unsigned long long* W0u = (const unsigned long long*)Whh0;
        const unsigned long long* Wxu = (const unsigned long long*)Wih1;
        const unsigned long long* W1u = (const unsigned long long*)Whh1;
        const unsigned long long* Wmu = (const unsigned long long*)W1;
        unsigned long long w0[16], wx[16], w1[16], wm[16];
#pragma unroll
        for (int m = 0; m < 16; m++) {
            const int k = kh * 16 + m;
            w0[m] = W0u[j * 32 + k];
            wx[m] = Wxu[j * 32 + k];
            w1[m] = W1u[j * 32 + k];
            wm[m] = Wmu[j * 32 + k];
        }
        const float bias1g = lead ? (b_ih1[j] + b_hh1[j]) : 0.f;
        const float b1m    = lead ? b1[j] : 0.f;

        if (lead) {
            h0sm[bl][0][j] = 0.f;   // h0_{-1}
            h1sm[bl][0][j] = 0.f;   // h1_{-2}
        }

        float* zb = zout + b * T_ * 64;

        NAMED_BAR(barid, 192);

        int p = 0;
        for (int tb = 0; tb < T_; tb += PF) {
#pragma unroll
            for (int u = 0; u < PF; u++) {
                const int i = tb + u;
                const float xv = lead ? xir[bl][i & 7][j] : 0.f;

                // h0sm[bl][p] = h0_{i-1}, h1sm[bl][p] = h1_{i-2}
                unsigned long long a0 = pack2(xv, 0.f), a1 = 0ull;       // Whh0.h0
                unsigned long long c0 = pack2(bias1g, 0.f), c1 = 0ull;   // Wih1.h0
                unsigned long long d0 = 0ull, d1 = 0ull;                 // Whh1.h1
                unsigned long long m0 = pack2(b1m, 0.f), m1 = 0ull;      // W1.h1
                const ulonglong2* hp0 = (const ulonglong2*)&h0sm[bl][p][kh * 32];
                const ulonglong2* hp1 = (const ulonglong2*)&h1sm[bl][p][kh * 32];
#pragma unroll
                for (int m = 0; m < 16; m += 2) {
                    ulonglong2 v = hp0[m >> 1];   // h0_{i-1}: one load, two uses
                    ulonglong2 g = hp1[m >> 1];   // h1_{i-2}: one load, two uses
                    a0 = fma2(w0[m],     v.x, a0);
                    a1 = fma2(w0[m + 1], v.y, a1);
                    c0 = fma2(wx[m],     v.x, c0);
                    c1 = fma2(wx[m + 1], v.y, c1);
                    d0 = fma2(w1[m],     g.x, d0);
                    d1 = fma2(w1[m + 1], g.y, d1);
                    m0 = fma2(wm[m],     g.x, m0);
                    m1 = fma2(wm[m + 1], g.y, m1);
                }
                float s0, s1, e0, e1, z0, z1;
                unpack2(add2(a0, a1), s0, s1);
                unpack2(add2(add2(c0, c1), add2(d0, d1)), e0, e1);
                unpack2(add2(m0, m1), z0, z1);
                float sh = s0 + s1;
                float eh = e0 + e1;
                float zh = z0 + z1;
                sh += __shfl_xor_sync(0xffffffffu, sh, 16);   // combine K-halves
                eh += __shfl_xor_sync(0xffffffffu, eh, 16);
                zh += __shfl_xor_sync(0xffffffffu, zh, 16);

                const float h0v = fast_tanh(sh);
                float h1v = fast_tanh(eh);          // = h1_{i-1}
                if (i == 0) h1v = 0.f;              // h1_{-1} := 0
                const float zv = fmaxf(zh, 0.f);    // = z_{i-2}

                if (lead) {
                    h0sm[bl][p ^ 1][j] = h0v;
                    h1sm[bl][p ^ 1][j] = h1v;
                    if (i >= 2) zb[(i - 2) * 64 + j] = zv;
                }
                NAMED_BAR(barid, 192);
                p ^= 1;
            }
        }

        // Epilogue step 1: h1_{T-1} and z_{T-2} (producers have exited)
        {
            unsigned long long c0 = pack2(bias1g, 0.f), c1 = 0ull;
            unsigned long long d0 = 0ull, d1 = 0ull;
            unsigned long long m0 = pack2(b1m, 0.f), m1 = 0ull;
            const ulonglong2* hp0 = (const ulonglong2*)&h0sm[bl][p][kh * 32];
            const ulonglong2* hp1 = (const ulonglong2*)&h1sm[bl][p][kh * 32];
#pragma unroll
            for (int m = 0; m < 16; m += 2) {
                ulonglong2 v = hp0[m >> 1];   // h0_{T-1}
                ulonglong2 g = hp1[m >> 1];   // h1_{T-2}
                c0 = fma2(wx[m],     v.x, c0);
                c1 = fma2(wx[m + 1], v.y, c1);
                d0 = fma2(w1[m],     g.x, d0);
                d1 = fma2(w1[m + 1], g.y, d1);
                m0 = fma2(wm[m],     g.x, m0);
                m1 = fma2(wm[m + 1], g.y, m1);
            }
            float e0, e1, z0, z1;
            unpack2(add2(add2(c0, c1), add2(d0, d1)), e0, e1);
            unpack2(add2(m0, m1), z0, z1);
            float eh = e0 + e1;
            float zh = z0 + z1;
            eh += __shfl_xor_sync(0xffffffffu, eh, 16);
            zh += __shfl_xor_sync(0xffffffffu, zh, 16);
            if (lead) {
                zb[(T_ - 2) * 64 + j] = fmaxf(zh, 0.f);
                h1sm[bl][p ^ 1][j] = fast_tanh(eh);   // h1_{T-1}
            }
            NAMED_BAR(barid, 128);
        }
        // Epilogue step 2: z_{T-1} = relu(W1 h1_{T-1} + b1)
        {
            unsigned long long m0 = pack2(b1m, 0.f), m1 = 0ull;
            const ulonglong2* hp1 = (const ulonglong2*)&h1sm[bl][p ^ 1][kh * 32];
#pragma unroll
            for (int m = 0; m < 16; m += 2) {
                ulonglong2 g = hp1[m >> 1];
                m0 = fma2(wm[m],     g.x, m0);
                m1 = fma2(wm[m + 1], g.y, m1);
            }
            float z0, z1;
            unpack2(add2(m0, m1), z0, z1);
            float zh = z0 + z1;
            zh += __shfl_xor_sync(0xffffffffu, zh, 16);
            if (lead) zb[(T_ - 1) * 64 + j] = fmaxf(zh, 0.f);
        }
    } else {
        // ======================= PRODUCER =======================
        const int pw = wid - 8;
        const int bl = pw >> 1;           // batch slot
        const int pq = pw & 1;            // producer warp within batch
        const int jp = pq * 32 + l;       // owned xin output (full K)
        const long b = blockIdx.x * 2 + bl;
        const int barid = bl + 1;
        const unsigned long long* xbu =
            (const unsigned long long*)(x + b * T_ * 64);

        const unsigned long long* Wiu = (const unsigned long long*)Wih0;
        unsigned long long wi[32];
#pragma unroll
        for (int k = 0; k < 32; k++) wi[k] = Wiu[jp * 32 + k];
        const float bias0 = b_ih0[jp] + b_hh0[jp];

        // prologue: raw x_0, x_1 into ring; xin_0 into xir[0]; x_2,x_3 to regs
        if (pq == 0) {
            xraw[bl][0][l] = xbu[l];
            xraw[bl][1][l] = xbu[32 + l];
        }
        NAMED_BAR(3 + bl, 64);   // producer pair only: xraw[0..1] visible
        {
            unsigned long long a0 = pack2(bias0, 0.f), a1 = 0ull, a2 = 0ull, a3 = 0ull;
            const ulonglong2* xp = (const ulonglong2*)&xraw[bl][0][0];
#pragma unroll
            for (int m = 0; m < 32; m += 4) {
                ulonglong2 v0 = xp[m >> 1], v1 = xp[(m >> 1) + 1];
                a0 = fma2(wi[m],     v0.x, a0);
                a1 = fma2(wi[m + 1], v0.y, a1);
                a2 = fma2(wi[m + 2], v1.x, a2);
                a3 = fma2(wi[m + 3], v1.y, a3);
            }
            float s0, s1;
            unpack2(add2(add2(a0, a1), add2(a2, a3)), s0, s1);
            xir[bl][0][jp] = s0 + s1;
        }
        unsigned long long xr0 = 0ull, xr1 = 0ull;
        if (pq == 0) { xr0 = xbu[2 * 32 + l]; xr1 = xbu[3 * 32 + l]; }

        NAMED_BAR(barid, 192);

        for (int tb = 0; tb < T_; tb += PF) {
#pragma unroll
            for (int u = 0; u < PF; u++) {
                const int n = tb + u;
                if (pq == 0) {
                    if (n + 2 < T_) xraw[bl][(n + 2) & 7][l] = (u & 1) ? xr1 : xr0;
                    if (n + 4 < T_) {
                        if (u & 1) xr1 = xbu[(n + 4) * 32 + l];
                        else       xr0 = xbu[(n + 4) * 32 + l];
                    }
                }
                if (n + 1 < T_) {
                    // xin_{n+1} from xraw slot (n+1)&7 (written interval n-1)
                    unsigned long long a0 = pack2(bias0, 0.f), a1 = 0ull,
                                       a2 = 0ull, a3 = 0ull;
                    const ulonglong2* xp =
                        (const ulonglong2*)&xraw[bl][(n + 1) & 7][0];
#pragma unroll
                    for (int m = 0; m < 32; m += 4) {
                        ulonglong2 v0 = xp[m >> 1], v1 = xp[(m >> 1) + 1];
                        a0 = fma2(wi[m],     v0.x, a0);
                        a1 = fma2(wi[m + 1], v0.y, a1);
                        a2 = fma2(wi[m + 2], v1.x, a2);
                        a3 = fma2(wi[m + 3], v1.y, a3);
                    }
                    float s0, s1;
                    unpack2(add2(add2(a0, a1), add2(a2, a3)), s0, s1);
                    xir[bl][(n + 1) & 7][jp] = s0 + s1;
                }
                NAMED_BAR(barid, 192);
            }
        }
        // producers exit; consumers continue with count-128 epilogue bars
    }
}

// ============================================================================
// w2: out[r][o] = sum_j W2[o][j] z[r][j] + b2[o]  (O=2). 8 rows/iter.
// (measured 34.7 us, 4 TB/s)
// ============================================================================
__global__ void __launch_bounds__(128) w2_kernel(
    const float* __restrict__ z, const float* __restrict__ W2,
    const float* __restrict__ b2, float* __restrict__ out, int nrows)
{
    const int l = threadIdx.x & 31;
    const int wrp = threadIdx.x >> 5;
    const unsigned long long* Zu  = (const unsigned long long*)z;
    const unsigned long long* W2u = (const unsigned long long*)W2;

    const unsigned long long w2a = W2u[l];        // (W2[0][2l], W2[0][2l+1])
    const unsigned long long w2b = W2u[32 + l];   // (W2[1][2l], W2[1][2l+1])
    const float b20 = b2[0], b21 = b2[1];

    const int  warpId = blockIdx.x * 4 + wrp;
    const int  nw     = gridDim.x * 4;
    const long stride = 8L * nw;

    for (long r = 8L * warpId; r < nrows; r += stride) {
        unsigned long long zv[8];
#pragma unroll
        for (int q = 0; q < 8; q++)
            zv[q] = (r + q < nrows) ? Zu[(r + q) * 32 + l] : 0ull;

        float p0[8], p1[8];
#pragma unroll
        for (int q = 0; q < 8; q++) {
            float a0, a1, c0, c1;
            unpack2(fma2(w2a, zv[q], 0ull), a0, a1);
            unpack2(fma2(w2b, zv[q], 0ull), c0, c1);
            p0[q] = a0 + a1;
            p1[q] = c0 + c1;
        }
#pragma unroll
        for (int off = 16; off; off >>= 1) {
#pragma unroll
            for (int q = 0; q < 8; q++) {
                p0[q] += __shfl_xor_sync(0xffffffffu, p0[q], off);
                p1[q] += __shfl_xor_sync(0xffffffffu, p1[q], off);
            }
        }
        if (l == 0) {
#pragma unroll
            for (int q = 0; q < 8; q++)
                if (r + q < nrows)
                    *reinterpret_cast<float2*>(&out[(r + q) * 2]) =
                        make_float2(p0[q] + b20, p1[q] + b21);
        }
    }
}

// ============================================================================
extern "C" void kernel_launch(void* const* d_in, const int* in_sizes, int n_in,
                              void* d_out, int out_size)
{
    const float* x     = (const float*)d_in[0];
    const float* W_ih0 = (const float*)d_in[1];
    const float* W_hh0 = (const float*)d_in[2];
    const float* b_ih0 = (const float*)d_in[3];
    const float* b_hh0 = (const float*)d_in[4];
    const float* W_ih1 = (const float*)d_in[5];
    const float* W_hh1 = (const float*)d_in[6];
    const float* b_ih1 = (const float*)d_in[7];
    const float* b_hh1 = (const float*)d_in[8];
    const float* W1    = (const float*)d_in[9];
    const float* b1    = (const float*)d_in[10];
    const float* W2    = (const float*)d_in[11];
    const float* b2    = (const float*)d_in[12];
    float* out = (float*)d_out;

    static float* bufB = nullptr;
    if (!bufB) cudaGetSymbolAddress((void**)&bufB, g_bufB);

    // input projection (producer warps) + both RNN layers + MLP W1 -> z
    fused_scan_kernel<<<B_ / 2, 384>>>(x, W_ih0, b_ih0, b_hh0,
                                       W_hh0, W_ih1, W_hh1,
                                       b_ih1, b_hh1, W1, b1, bufB);
    // out = z W2^T + b2
    w2_kernel<<<1024, 128>>>(bufB, W2, b2, out, NROWS);
}

// round 14
// speedup vs baseline: 1.1412x; 1.1412x over previous
#include <cuda_runtime.h>

#define B_  256
#define T_  2048
#define H_  64
#define O_  2
#define NROWS (B_ * T_)
#define PF  4   // fused-scan xin prefetch depth (T_ % PF == 0)

// Scratch (device globals — no allocation allowed in kernel_launch)
__device__ float g_bufA[NROWS * H_];
__device__ float g_bufB[NROWS * H_];

// ---------- packed f32x2 helpers (sm_103a FFMA2 path) ----------
static __device__ __forceinline__ unsigned long long pack2(float lo, float hi) {
    unsigned long long r;
    asm("mov.b64 %0, {%1, %2};" : "=l"(r) : "f"(lo), "f"(hi));
    return r;
}
static __device__ __forceinline__ void unpack2(unsigned long long v, float& a, float& b) {
    asm("mov.b64 {%0, %1}, %2;" : "=f"(a), "=f"(b) : "l"(v));
}
static __device__ __forceinline__ unsigned long long fma2(unsigned long long a,
                                                          unsigned long long b,
                                                          unsigned long long c) {
    unsigned long long d;
    asm("fma.rn.f32x2 %0, %1, %2, %3;" : "=l"(d) : "l"(a), "l"(b), "l"(c));
    return d;
}
static __device__ __forceinline__ unsigned long long add2(unsigned long long a,
                                                          unsigned long long b) {
    unsigned long long d;
    asm("add.rn.f32x2 %0, %1, %2;" : "=l"(d) : "l"(a), "l"(b));
    return d;
}

// Fast tanh, rel err ~1e-7, saturates correctly.
static __device__ __forceinline__ float fast_tanh(float x) {
    float e = __expf(2.0f * x);
    return 1.0f - __fdividef(2.0f, e + 1.0f);
}

#define NAMED_BAR(id, cnt) asm volatile("bar.sync %0, %1;" :: "r"(id), "r"(cnt) : "memory")

// ============================================================================
// gemm64 (half-split, 4 rows/iter, high occupancy):
// Warp = (rowQuad, outputHalf): lane owns output j = half*32 + l for rows
// r..r+3. Only 32 weight u64 (64 regs) -> ~110 regs -> 4 blocks/SM
// (16 warps/SM, 16KB loads in flight -> ~4 TB/s). The two warps of a pair
// fetch the same 4 rows; duplicates dedup in L2, DRAM traffic unchanged.
// ============================================================================
__global__ void __launch_bounds__(128, 4) gemm64_kernel(
    const float* __restrict__ in, const float* __restrict__ W,
    const float* __restrict__ ba, const float* __restrict__ bb,
    float* __restrict__ out, int nrows)
{
    __shared__ __align__(16) unsigned long long xsm[4][2][4][32]; // [warp][buf][row][pair]
    const int l   = threadIdx.x & 31;
    const int wrp = threadIdx.x >> 5;
    const unsigned long long* Wu = (const unsigned long long*)W;
    const unsigned long long* Iu = (const unsigned long long*)in;

    const int  warpId = blockIdx.x * 4 + wrp;
    const int  half   = warpId & 1;
    const long pair   = warpId >> 1;
    const long npair  = (long)gridDim.x * 2;
    const int  j      = half * 32 + l;

    unsigned long long w[32];
#pragma unroll
    for (int k = 0; k < 32; k++) w[k] = Wu[j * 32 + k];
    const float bias = ba[j] + bb[j];

    const long stride = 4L * npair;
    long r = 4L * pair;
    if (r >= nrows) return;

    unsigned long long xv[4];
#pragma unroll
    for (int q = 0; q < 4; q++)
        xv[q] = (r + q < nrows) ? Iu[(r + q) * 32 + l] : 0ull;
    int buf = 0;

    while (r < nrows) {
#pragma unroll
        for (int q = 0; q < 4; q++) xsm[wrp][buf][q][l] = xv[q];
        __syncwarp();

        long rn = r + stride;
        if (rn < nrows) {
#pragma unroll
            for (int q = 0; q < 4; q++)
                xv[q] = (rn + q < nrows) ? Iu[(rn + q) * 32 + l] : 0ull;
        }

        unsigned long long a[4], b[4];
#pragma unroll
        for (int q = 0; q < 4; q++) { a[q] = pack2(bias, 0.f); b[q] = 0ull; }
#pragma unroll
        for (int k = 0; k < 32; k += 2) {
#pragma unroll
            for (int q = 0; q < 4; q++) {
                ulonglong2 v = ((const ulonglong2*)&xsm[wrp][buf][q][0])[k >> 1];
                a[q] = fma2(w[k],     v.x, a[q]);
                b[q] = fma2(w[k + 1], v.y, b[q]);
            }
        }
#pragma unroll
        for (int q = 0; q < 4; q++) {
            if (r + q < nrows) {
                float s0, s1;
                unpack2(add2(a[q], b[q]), s0, s1);
                out[(r + q) * 64 + j] = s0 + s1;
            }
        }

        buf ^= 1;
        r = rn;
    }
}

// ============================================================================
// fused_scan + MLP-W1 (R12 config, measured ~745 us — at its plateau):
//   h0_i     = tanh(xin0_i + W_hh0 h0_{i-1})
//   h1_{i-1} = tanh(W_ih1 h0_{i-1} + b1rnn + W_hh1 h1_{i-2})
//   z_{i-2}  = relu(W1 h1_{i-2} + b1mlp)       <- reuses the h1_{i-2} loads
// Block = 256 thr = 2 batches x 4 warps; per-batch named barrier.
// Lane owns output j = wq*16+(l&15), K-half kh=l>>4; halves via shfl_xor(16).
// ============================================================================
__global__ void __launch_bounds__(256) fused_scan_kernel(
    const float* __restrict__ xin0,
    const float* __restrict__ Whh0, const float* __restrict__ Wih1,
    const float* __restrict__ Whh1,
    const float* __restrict__ b_ih1, const float* __restrict__ b_hh1,
    const float* __restrict__ W1,   const float* __restrict__ b1,
    float* __restrict__ zout)
{
    __shared__ __align__(16) float h0sm[2][2][64];
    __shared__ __align__(16) float h1sm[2][2][64];
    const int l     = threadIdx.x & 31;
    const int wid   = threadIdx.x >> 5;
    const int bl    = wid >> 2;            // batch slot (0..1)
    const int wq    = wid & 3;             // warp-in-batch
    const int j     = wq * 16 + (l & 15);  // owned output
    const int kh    = l >> 4;              // K-half
    const bool lead = (l < 16);
    const long b    = blockIdx.x * 2 + bl;
    const int barid = bl + 1;

    const unsigned long long* W0u = (const unsigned long long*)Whh0;
    const unsigned long long* Wxu = (const unsigned long long*)Wih1;
    const unsigned long long* W1u = (const unsigned long long*)Whh1;
    const unsigned long long* Wmu = (const unsigned long long*)W1;
    unsigned long long w0[16], wx[16], w1[16], wm[16];
#pragma unroll
    for (int m = 0; m < 16; m++) {
        const int k = kh * 16 + m;
        w0[m] = W0u[j * 32 + k];
        wx[m] = Wxu[j * 32 + k];
        w1[m] = W1u[j * 32 + k];
        wm[m] = Wmu[j * 32 + k];
    }
    const float bias1g = lead ? (b_ih1[j] + b_hh1[j]) : 0.f;
    const float b1m    = lead ? b1[j] : 0.f;

    if (lead) {
        h0sm[bl][0][j] = 0.f;   // h0_{-1}
        h1sm[bl][0][j] = 0.f;   // h1_{-2}
    }

    const float* xb = xin0 + b * T_ * 64;
    float*       zb = zout + b * T_ * 64;

    float xs[PF];
#pragma unroll
    for (int s = 0; s < PF; s++) xs[s] = xb[s * 64 + j];

    NAMED_BAR(barid, 128);

    int p = 0;
    for (int tb = 0; tb < T_; tb += PF) {
#pragma unroll
        for (int u = 0; u < PF; u++) {
            const int i = tb + u;
            const float xv = lead ? xs[u] : 0.f;
            if (i + PF < T_) xs[u] = xb[(i + PF) * 64 + j];

            // h0sm[bl][p] = h0_{i-1}, h1sm[bl][p] = h1_{i-2}
            unsigned long long a0 = pack2(xv, 0.f), a1 = 0ull;       // Whh0.h0
            unsigned long long c0 = pack2(bias1g, 0.f), c1 = 0ull;   // Wih1.h0
            unsigned long long d0 = 0ull, d1 = 0ull;                 // Whh1.h1
            unsigned long long m0 = pack2(b1m, 0.f), m1 = 0ull;      // W1.h1
            const ulonglong2* hp0 = (const ulonglong2*)&h0sm[bl][p][kh * 32];
            const ulonglong2* hp1 = (const ulonglong2*)&h1sm[bl][p][kh * 32];
#pragma unroll
            for (int m = 0; m < 16; m += 2) {
                ulonglong2 v = hp0[m >> 1];   // h0_{i-1}: one load, two uses
                ulonglong2 g = hp1[m >> 1];   // h1_{i-2}: one load, two uses
                a0 = fma2(w0[m],     v.x, a0);
                a1 = fma2(w0[m + 1], v.y, a1);
                c0 = fma2(wx[m],     v.x, c0);
                c1 = fma2(wx[m + 1], v.y, c1);
                d0 = fma2(w1[m],     g.x, d0);
                d1 = fma2(w1[m + 1], g.y, d1);
                m0 = fma2(wm[m],     g.x, m0);
                m1 = fma2(wm[m + 1], g.y, m1);
            }
            float s0, s1, e0, e1, z0, z1;
            unpack2(add2(a0, a1), s0, s1);
            unpack2(add2(add2(c0, c1), add2(d0, d1)), e0, e1);
            unpack2(add2(m0, m1), z0, z1);
            float sh = s0 + s1;
            float eh = e0 + e1;
            float zh = z0 + z1;
            sh += __shfl_xor_sync(0xffffffffu, sh, 16);   // combine K-halves
            eh += __shfl_xor_sync(0xffffffffu, eh, 16);
            zh += __shfl_xor_sync(0xffffffffu, zh, 16);

            const float h0v = fast_tanh(sh);
            float h1v = fast_tanh(eh);          // = h1_{i-1}
            if (i == 0) h1v = 0.f;              // h1_{-1} := 0
            const float zv = fmaxf(zh, 0.f);    // = z_{i-2}

            if (lead) {
                h0sm[bl][p ^ 1][j] = h0v;
                h1sm[bl][p ^ 1][j] = h1v;
                if (i >= 2) zb[(i - 2) * 64 + j] = zv;
            }
            NAMED_BAR(barid, 128);
            p ^= 1;
        }
    }

    // Epilogue step 1: h1_{T-1} and z_{T-2}
    {
        unsigned long long c0 = pack2(bias1g, 0.f), c1 = 0ull;
        unsigned long long d0 = 0ull, d1 = 0ull;
        unsigned long long m0 = pack2(b1m, 0.f), m1 = 0ull;
        const ulonglong2* hp0 = (const ulonglong2*)&h0sm[bl][p][kh * 32];
        const ulonglong2* hp1 = (const ulonglong2*)&h1sm[bl][p][kh * 32];
#pragma unroll
        for (int m = 0; m < 16; m += 2) {
            ulonglong2 v = hp0[m >> 1];   // h0_{T-1}
            ulonglong2 g = hp1[m >> 1];   // h1_{T-2}
            c0 = fma2(wx[m],     v.x, c0);
            c1 = fma2(wx[m + 1], v.y, c1);
            d0 = fma2(w1[m],     g.x, d0);
            d1 = fma2(w1[m + 1], g.y, d1);
            m0 = fma2(wm[m],     g.x, m0);
            m1 = fma2(wm[m + 1], g.y, m1);
        }
        float e0, e1, z0, z1;
        unpack2(add2(add2(c0, c1), add2(d0, d1)), e0, e1);
        unpack2(add2(m0, m1), z0, z1);
        float eh = e0 + e1;
        float zh = z0 + z1;
        eh += __shfl_xor_sync(0xffffffffu, eh, 16);
        zh += __shfl_xor_sync(0xffffffffu, zh, 16);
        if (lead) {
            zb[(T_ - 2) * 64 + j] = fmaxf(zh, 0.f);
            h1sm[bl][p ^ 1][j] = fast_tanh(eh);   // h1_{T-1}
        }
        NAMED_BAR(barid, 128);
    }
    // Epilogue step 2: z_{T-1} = relu(W1 h1_{T-1} + b1)
    {
        unsigned long long m0 = pack2(b1m, 0.f), m1 = 0ull;
        const ulonglong2* hp1 = (const ulonglong2*)&h1sm[bl][p ^ 1][kh * 32];
#pragma unroll
        for (int m = 0; m < 16; m += 2) {
            ulonglong2 g = hp1[m >> 1];
            m0 = fma2(wm[m],     g.x, m0);
            m1 = fma2(wm[m + 1], g.y, m1);
        }
        float z0, z1;
        unpack2(add2(m0, m1), z0, z1);
        float zh = z0 + z1;
        zh += __shfl_xor_sync(0xffffffffu, zh, 16);
        if (lead) zb[(T_ - 1) * 64 + j] = fmaxf(zh, 0.f);
    }
}

// ============================================================================
// w2: out[r][o] = sum_j W2[o][j] z[r][j] + b2[o]  (O=2). 8 rows/iter.
// (measured 34.7 us, 4 TB/s)
// ============================================================================
__global__ void __launch_bounds__(128) w2_kernel(
    const float* __restrict__ z, const float* __restrict__ W2,
    const float* __restrict__ b2, float* __restrict__ out, int nrows)
{
    const int l = threadIdx.x & 31;
    const int wrp = threadIdx.x >> 5;
    const unsigned long long* Zu  = (const unsigned long long*)z;
    const unsigned long long* W2u = (const unsigned long long*)W2;

    const unsigned long long w2a = W2u[l];        // (W2[0][2l], W2[0][2l+1])
    const unsigned long long w2b = W2u[32 + l];   // (W2[1][2l], W2[1][2l+1])
    const float b20 = b2[0], b21 = b2[1];

    const int  warpId = blockIdx.x * 4 + wrp;
    const int  nw     = gridDim.x * 4;
    const long stride = 8L * nw;

    for (long r = 8L * warpId; r < nrows; r += stride) {
        unsigned long long zv[8];
#pragma unroll
        for (int q = 0; q < 8; q++)
            zv[q] = (r + q < nrows) ? Zu[(r + q) * 32 + l] : 0ull;

        float p0[8], p1[8];
#pragma unroll
        for (int q = 0; q < 8; q++) {
            float a0, a1, c0, c1;
            unpack2(fma2(w2a, zv[q], 0ull), a0, a1);
            unpack2(fma2(w2b, zv[q], 0ull), c0, c1);
            p0[q] = a0 + a1;
            p1[q] = c0 + c1;
        }
#pragma unroll
        for (int off = 16; off; off >>= 1) {
#pragma unroll
            for (int q = 0; q < 8; q++) {
                p0[q] += __shfl_xor_sync(0xffffffffu, p0[q], off);
                p1[q] += __shfl_xor_sync(0xffffffffu, p1[q], off);
            }
        }
        if (l == 0) {
#pragma unroll
            for (int q = 0; q < 8; q++)
                if (r + q < nrows)
                    *reinterpret_cast<float2*>(&out[(r + q) * 2]) =
                        make_float2(p0[q] + b20, p1[q] + b21);
        }
    }
}

// ============================================================================
extern "C" void kernel_launch(void* const* d_in, const int* in_sizes, int n_in,
                              void* d_out, int out_size)
{
    const float* x     = (const float*)d_in[0];
    const float* W_ih0 = (const float*)d_in[1];
    const float* W_hh0 = (const float*)d_in[2];
    const float* b_ih0 = (const float*)d_in[3];
    const float* b_hh0 = (const float*)d_in[4];
    const float* W_ih1 = (const float*)d_in[5];
    const float* W_hh1 = (const float*)d_in[6];
    const float* b_ih1 = (const float*)d_in[7];
    const float* b_hh1 = (const float*)d_in[8];
    const float* W1    = (const float*)d_in[9];
    const float* b1    = (const float*)d_in[10];
    const float* W2    = (const float*)d_in[11];
    const float* b2    = (const float*)d_in[12];
    float* out = (float*)d_out;

    static float* bufA = nullptr;
    static float* bufB = nullptr;
    if (!bufA) {
        cudaGetSymbolAddress((void**)&bufA, g_bufA);
        cudaGetSymbolAddress((void**)&bufB, g_bufB);
    }

    // xin0 = x W_ih0^T + b_ih0 + b_hh0  (half-split, 4 blocks/SM)
    gemm64_kernel<<<2368, 128>>>(x, W_ih0, b_ih0, b_hh0, bufA, NROWS);
    // both RNN layers + MLP W1 -> z
    fused_scan_kernel<<<B_ / 2, 256>>>(bufA, W_hh0, W_ih1, W_hh1,
                                       b_ih1, b_hh1, W1, b1, bufB);
    // out = z W2^T + b2
    w2_kernel<<<1024, 128>>>(bufB, W2, b2, out, NROWS);
}

// round 16
// speedup vs baseline: 1.1679x; 1.0233x over previous
#include <cuda_runtime.h>

#define B_  256
#define T_  2048
#define H_  64
#define O_  2
#define NROWS (B_ * T_)
#define PF  4   // fused-scan xin prefetch depth (T_ % PF == 0)

// Scratch (device globals — no allocation allowed in kernel_launch)
__device__ float g_bufA[NROWS * H_];
__device__ float g_bufB[NROWS * H_];

// ---------- packed f32x2 helpers (sm_103a FFMA2 path) ----------
static __device__ __forceinline__ unsigned long long pack2(float lo, float hi) {
    unsigned long long r;
    asm("mov.b64 %0, {%1, %2};" : "=l"(r) : "f"(lo), "f"(hi));
    return r;
}
static __device__ __forceinline__ void unpack2(unsigned long long v, float& a, float& b) {
    asm("mov.b64 {%0, %1}, %2;" : "=f"(a), "=f"(b) : "l"(v));
}
static __device__ __forceinline__ unsigned long long fma2(unsigned long long a,
                                                          unsigned long long b,
                                                          unsigned long long c) {
    unsigned long long d;
    asm("fma.rn.f32x2 %0, %1, %2, %3;" : "=l"(d) : "l"(a), "l"(b), "l"(c));
    return d;
}
static __device__ __forceinline__ unsigned long long add2(unsigned long long a,
                                                          unsigned long long b) {
    unsigned long long d;
    asm("add.rn.f32x2 %0, %1, %2;" : "=l"(d) : "l"(a), "l"(b));
    return d;
}

// Fast tanh, rel err ~1e-7, saturates correctly.
static __device__ __forceinline__ float fast_tanh(float x) {
    float e = __expf(2.0f * x);
    return 1.0f - __fdividef(2.0f, e + 1.0f);
}

#define NAMED_BAR(id, cnt) asm volatile("bar.sync %0, %1;" :: "r"(id), "r"(cnt) : "memory")

// ============================================================================
// gemm64 (4 rows/iter, DEPTH-2 register prefetch):
// out[r][j] = sum_k in[r][k]*W[j][k] + ba[j] + bb[j]
// Two alternating 4-row prefetch sets (xvA/xvB) keep 2KB of DRAM reads in
// flight per warp (each LDG batch has ~2 compute bodies to land).
// 238 regs -> still 2 blocks/SM (enforced by __launch_bounds__(128,2)).
// ============================================================================
__global__ void __launch_bounds__(128, 2) gemm64_kernel(
    const float* __restrict__ in, const float* __restrict__ W,
    const float* __restrict__ ba, const float* __restrict__ bb,
    float* __restrict__ out, int nrows)
{
    __shared__ __align__(16) unsigned long long xsm[4][2][4][32]; // [warp][buf][row][pair]
    const int l   = threadIdx.x & 31;
    const int wrp = threadIdx.x >> 5;
    const unsigned long long* Wu = (const unsigned long long*)W;
    const unsigned long long* Iu = (const unsigned long long*)in;

    unsigned long long wl[32], wh[32];
#pragma unroll
    for (int k = 0; k < 32; k++) {
        wl[k] = Wu[l * 32 + k];
        wh[k] = Wu[(l + 32) * 32 + k];
    }
    const float biasl = ba[l] + bb[l];
    const float biash = ba[l + 32] + bb[l + 32];

    const int  warpId = blockIdx.x * 4 + wrp;
    const int  nw     = gridDim.x * 4;
    const long stride = 4L * nw;

    long r = 4L * warpId;
    if (r >= nrows) return;

    unsigned long long xvA[4], xvB[4];
#pragma unroll
    for (int q = 0; q < 4; q++) {
        xvA[q] = (r + q < nrows) ? Iu[(r + q) * 32 + l] : 0ull;
        const long rB = r + stride;
        xvB[q] = (rB + q < nrows) ? Iu[(rB + q) * 32 + l] : 0ull;
    }
    int buf = 0;

    while (r < nrows) {
        // ---- sub-iteration A (data in xvA) ----
        {
#pragma unroll
            for (int q = 0; q < 4; q++) xsm[wrp][buf][q][l] = xvA[q];
            __syncwarp();
            const long rp = r + 2 * stride;            // refill xvA 2 iters ahead
            if (rp < nrows) {
#pragma unroll
                for (int q = 0; q < 4; q++)
                    xvA[q] = (rp + q < nrows) ? Iu[(rp + q) * 32 + l] : 0ull;
            }

            unsigned long long aL[4], aH[4], bL[4], bH[4];
#pragma unroll
            for (int q = 0; q < 4; q++) {
                aL[q] = pack2(biasl, 0.f); bL[q] = 0ull;
                aH[q] = pack2(biash, 0.f); bH[q] = 0ull;
            }
#pragma unroll
            for (int k = 0; k < 32; k += 2) {
#pragma unroll
                for (int q = 0; q < 4; q++) {
                    ulonglong2 v = ((const ulonglong2*)&xsm[wrp][buf][q][0])[k >> 1];
                    aL[q] = fma2(wl[k],     v.x, aL[q]);
                    bL[q] = fma2(wl[k + 1], v.y, bL[q]);
                    aH[q] = fma2(wh[k],     v.x, aH[q]);
                    bH[q] = fma2(wh[k + 1], v.y, bH[q]);
                }
            }
#pragma unroll
            for (int q = 0; q < 4; q++) {
                if (r + q < nrows) {
                    float s0, s1, t0, t1;
                    unpack2(add2(aL[q], bL[q]), s0, s1);
                    unpack2(add2(aH[q], bH[q]), t0, t1);
                    out[(r + q) * 64 + l]      = s0 + s1;
                    out[(r + q) * 64 + 32 + l] = t0 + t1;
                }
            }
            buf ^= 1;
            r += stride;
        }
        if (r >= nrows) break;

        // ---- sub-iteration B (data in xvB) ----
        {
#pragma unroll
            for (int q = 0; q < 4; q++) xsm[wrp][buf][q][l] = xvB[q];
            __syncwarp();
            const long rp = r + 2 * stride;            // refill xvB 2 iters ahead
            if (rp < nrows) {
#pragma unroll
                for (int q = 0; q < 4; q++)
                    xvB[q] = (rp + q < nrows) ? Iu[(rp + q) * 32 + l] : 0ull;
            }

            unsigned long long aL[4], aH[4], bL[4], bH[4];
#pragma unroll
            for (int q = 0; q < 4; q++) {
                aL[q] = pack2(biasl, 0.f); bL[q] = 0ull;
                aH[q] = pack2(biash, 0.f); bH[q] = 0ull;
            }
#pragma unroll
            for (int k = 0; k < 32; k += 2) {
#pragma unroll
                for (int q = 0; q < 4; q++) {
                    ulonglong2 v = ((const ulonglong2*)&xsm[wrp][buf][q][0])[k >> 1];
                    aL[q] = fma2(wl[k],     v.x, aL[q]);
                    bL[q] = fma2(wl[k + 1], v.y, bL[q]);
                    aH[q] = fma2(wh[k],     v.x, aH[q]);
                    bH[q] = fma2(wh[k + 1], v.y, bH[q]);
                }
            }
#pragma unroll
            for (int q = 0; q < 4; q++) {
                if (r + q < nrows) {
                    float s0, s1, t0, t1;
                    unpack2(add2(aL[q], bL[q]), s0, s1);
                    unpack2(add2(aH[q], bH[q]), t0, t1);
                    out[(r + q) * 64 + l]      = s0 + s1;
                    out[(r + q) * 64 + 32 + l] = t0 + t1;
                }
            }
            buf ^= 1;
            r += stride;
        }
    }
}

// ============================================================================
// fused_scan + MLP-W1 (R12 config — at its measured plateau, ~745 us):
//   h0_i     = tanh(xin0_i + W_hh0 h0_{i-1})
//   h1_{i-1} = tanh(W_ih1 h0_{i-1} + b1rnn + W_hh1 h1_{i-2})
//   z_{i-2}  = relu(W1 h1_{i-2} + b1mlp)
// Block = 256 thr = 2 batches x 4 warps; per-batch named barrier.
// ============================================================================
__global__ void __launch_bounds__(256) fused_scan_kernel(
    const float* __restrict__ xin0,
    const float* __restrict__ Whh0, const float* __restrict__ Wih1,
    const float* __restrict__ Whh1,
    const float* __restrict__ b_ih1, const float* __restrict__ b_hh1,
    const float* __restrict__ W1,   const float* __restrict__ b1,
    float* __restrict__ zout)
{
    __shared__ __align__(16) float h0sm[2][2][64];
    __shared__ __align__(16) float h1sm[2][2][64];
    const int l     = threadIdx.x & 31;
    const int wid   = threadIdx.x >> 5;
    const int bl    = wid >> 2;            // batch slot (0..1)
    const int wq    = wid & 3;             // warp-in-batch
    const int j     = wq * 16 + (l & 15);  // owned output
    const int kh    = l >> 4;              // K-half
    const bool lead = (l < 16);
    const long b    = blockIdx.x * 2 + bl;
    const int barid = bl + 1;

    const unsigned long long* W0u = (const unsigned long long*)Whh0;
    const unsigned long long* Wxu = (const unsigned long long*)Wih1;
    const unsigned long long* W1u = (const unsigned long long*)Whh1;
    const unsigned long long* Wmu = (const unsigned long long*)W1;
    unsigned long long w0[16], wx[16], w1[16], wm[16];
#pragma unroll
    for (int m = 0; m < 16; m++) {
        const int k = kh * 16 + m;
        w0[m] = W0u[j * 32 + k];
        wx[m] = Wxu[j * 32 + k];
        w1[m] = W1u[j * 32 + k];
        wm[m] = Wmu[j * 32 + k];
    }
    const float bias1g = lead ? (b_ih1[j] + b_hh1[j]) : 0.f;
    const float b1m    = lead ? b1[j] : 0.f;

    if (lead) {
        h0sm[bl][0][j] = 0.f;   // h0_{-1}
        h1sm[bl][0][j] = 0.f;   // h1_{-2}
    }

    const float* xb = xin0 + b * T_ * 64;
    float*       zb = zout + b * T_ * 64;

    float xs[PF];
#pragma unroll
    for (int s = 0; s < PF; s++) xs[s] = xb[s * 64 + j];

    NAMED_BAR(barid, 128);

    int p = 0;
    for (int tb = 0; tb < T_; tb += PF) {
#pragma unroll
        for (int u = 0; u < PF; u++) {
            const int i = tb + u;
            const float xv = lead ? xs[u] : 0.f;
            if (i + PF < T_) xs[u] = xb[(i + PF) * 64 + j];

            unsigned long long a0 = pack2(xv, 0.f), a1 = 0ull;       // Whh0.h0
            unsigned long long c0 = pack2(bias1g, 0.f), c1 = 0ull;   // Wih1.h0
            unsigned long long d0 = 0ull, d1 = 0ull;                 // Whh1.h1
            unsigned long long m0 = pack2(b1m, 0.f), m1 = 0ull;      // W1.h1
            const ulonglong2* hp0 = (const ulonglong2*)&h0sm[bl][p][kh * 32];
            const ulonglong2* hp1 = (const ulonglong2*)&h1sm[bl][p][kh * 32];
#pragma unroll
            for (int m = 0; m < 16; m += 2) {
                ulonglong2 v = hp0[m >> 1];   // h0_{i-1}: one load, two uses
                ulonglong2 g = hp1[m >> 1];   // h1_{i-2}: one load, two uses
                a0 = fma2(w0[m],     v.x, a0);
                a1 = fma2(w0[m + 1], v.y, a1);
                c0 = fma2(wx[m],     v.x, c0);
                c1 = fma2(wx[m + 1], v.y, c1);
                d0 = fma2(w1[m],     g.x, d0);
                d1 = fma2(w1[m + 1], g.y, d1);
                m0 = fma2(wm[m],     g.x, m0);
                m1 = fma2(wm[m + 1], g.y, m1);
            }
            float s0, s1, e0, e1, z0, z1;
            unpack2(add2(a0, a1), s0, s1);
            unpack2(add2(add2(c0, c1), add2(d0, d1)), e0, e1);
            unpack2(add2(m0, m1), z0, z1);
            float sh = s0 + s1;
            float eh = e0 + e1;
            float zh = z0 + z1;
            sh += __shfl_xor_sync(0xffffffffu, sh, 16);   // combine K-halves
            eh += __shfl_xor_sync(0xffffffffu, eh, 16);
            zh += __shfl_xor_sync(0xffffffffu, zh, 16);

            const float h0v = fast_tanh(sh);
            float h1v = fast_tanh(eh);          // = h1_{i-1}
            if (i == 0) h1v = 0.f;              // h1_{-1} := 0
            const float zv = fmaxf(zh, 0.f);    // = z_{i-2}

            if (lead) {
                h0sm[bl][p ^ 1][j] = h0v;
                h1sm[bl][p ^ 1][j] = h1v;
                if (i >= 2) zb[(i - 2) * 64 + j] = zv;
            }
            NAMED_BAR(barid, 128);
            p ^= 1;
        }
    }

    // Epilogue step 1: h1_{T-1} and z_{T-2}
    {
        unsigned long long c0 = pack2(bias1g, 0.f), c1 = 0ull;
        unsigned long long d0 = 0ull, d1 = 0ull;
        unsigned long long m0 = pack2(b1m, 0.f), m1 = 0ull;
        const ulonglong2* hp0 = (const ulonglong2*)&h0sm[bl][p][kh * 32];
        const ulonglong2* hp1 = (const ulonglong2*)&h1sm[bl][p][kh * 32];
#pragma unroll
        for (int m = 0; m < 16; m += 2) {
            ulonglong2 v = hp0[m >> 1];   // h0_{T-1}
            ulonglong2 g = hp1[m >> 1];   // h1_{T-2}
            c0 = fma2(wx[m],     v.x, c0);
            c1 = fma2(wx[m + 1], v.y, c1);
            d0 = fma2(w1[m],     g.x, d0);
            d1 = fma2(w1[m + 1], g.y, d1);
            m0 = fma2(wm[m],     g.x, m0);
            m1 = fma2(wm[m + 1], g.y, m1);
        }
        float e0, e1, z0, z1;
        unpack2(add2(add2(c0, c1), add2(d0, d1)), e0, e1);
        unpack2(add2(m0, m1), z0, z1);
        float eh = e0 + e1;
        float zh = z0 + z1;
        eh += __shfl_xor_sync(0xffffffffu, eh, 16);
        zh += __shfl_xor_sync(0xffffffffu, zh, 16);
        if (lead) {
            zb[(T_ - 2) * 64 + j] = fmaxf(zh, 0.f);
            h1sm[bl][p ^ 1][j] = fast_tanh(eh);   // h1_{T-1}
        }
        NAMED_BAR(barid, 128);
    }
    // Epilogue step 2: z_{T-1} = relu(W1 h1_{T-1} + b1)
    {
        unsigned long long m0 = pack2(b1m, 0.f), m1 = 0ull;
        const ulonglong2* hp1 = (const ulonglong2*)&h1sm[bl][p ^ 1][kh * 32];
#pragma unroll
        for (int m = 0; m < 16; m += 2) {
            ulonglong2 g = hp1[m >> 1];
            m0 = fma2(wm[m],     g.x, m0);
            m1 = fma2(wm[m + 1], g.y, m1);
        }
        float z0, z1;
        unpack2(add2(m0, m1), z0, z1);
        float zh = z0 + z1;
        zh += __shfl_xor_sync(0xffffffffu, zh, 16);
        if (lead) zb[(T_ - 1) * 64 + j] = fmaxf(zh, 0.f);
    }
}

// ============================================================================
// w2: out[r][o] = sum_j W2[o][j] z[r][j] + b2[o]  (O=2). 8 rows/iter.
// (measured 34.7 us, ~4 TB/s)
// ============================================================================
__global__ void __launch_bounds__(128) w2_kernel(
    const float* __restrict__ z, const float* __restrict__ W2,
    const float* __restrict__ b2, float* __restrict__ out, int nrows)
{
    const int l = threadIdx.x & 31;
    const int wrp = threadIdx.x >> 5;
    const unsigned long long* Zu  = (const unsigned long long*)z;
    const unsigned long long* W2u = (const unsigned long long*)W2;

    const unsigned long long w2a = W2u[l];
    const unsigned long long w2b = W2u[32 + l];
    const float b20 = b2[0], b21 = b2[1];

    const int  warpId = blockIdx.x * 4 + wrp;
    const int  nw     = gridDim.x * 4;
    const long stride = 8L * nw;

    for (long r = 8L * warpId; r < nrows; r += stride) {
        unsigned long long zv[8];
#pragma unroll
        for (int q = 0; q < 8; q++)
            zv[q] = (r + q < nrows) ? Zu[(r + q) * 32 + l] : 0ull;

        float p0[8], p1[8];
#pragma unroll
        for (int q = 0; q < 8; q++) {
            float a0, a1, c0, c1;
            unpack2(fma2(w2a, zv[q], 0ull), a0, a1);
            unpack2(fma2(w2b, zv[q], 0ull), c0, c1);
            p0[q] = a0 + a1;
            p1[q] = c0 + c1;
        }
#pragma unroll
        for (int off = 16; off; off >>= 1) {
#pragma unroll
            for (int q = 0; q < 8; q++) {
                p0[q] += __shfl_xor_sync(0xffffffffu, p0[q], off);
                p1[q] += __shfl_xor_sync(0xffffffffu, p1[q], off);
            }
        }
        if (l == 0) {
#pragma unroll
            for (int q = 0; q < 8; q++)
                if (r + q < nrows)
                    *reinterpret_cast<float2*>(&out[(r + q) * 2]) =
                        make_float2(p0[q] + b20, p1[q] + b21);
        }
    }
}

// ============================================================================
extern "C" void kernel_launch(void* const* d_in, const int* in_sizes, int n_in,
                              void* d_out, int out_size)
{
    const float* x     = (const float*)d_in[0];
    const float* W_ih0 = (const float*)d_in[1];
    const float* W_hh0 = (const float*)d_in[2];
    const float* b_ih0 = (const float*)d_in[3];
    const float* b_hh0 = (const float*)d_in[4];
    const float* W_ih1 = (const float*)d_in[5];
    const float* W_hh1 = (const float*)d_in[6];
    const float* b_ih1 = (const float*)d_in[7];
    const float* b_hh1 = (const float*)d_in[8];
    const float* W1    = (const float*)d_in[9];
    const float* b1    = (const float*)d_in[10];
    const float* W2    = (const float*)d_in[11];
    const float* b2    = (const float*)d_in[12];
    float* out = (float*)d_out;

    static float* bufA = nullptr;
    static float* bufB = nullptr;
    if (!bufA) {
        cudaGetSymbolAddress((void**)&bufA, g_bufA);
        cudaGetSymbolAddress((void**)&bufB, g_bufB);
    }

    // xin0 = x W_ih0^T + b_ih0 + b_hh0   (depth-2 prefetch)
    gemm64_kernel<<<1184, 128>>>(x, W_ih0, b_ih0, b_hh0, bufA, NROWS);
    // both RNN layers + MLP W1 -> z
    fused_scan_kernel<<<B_ / 2, 256>>>(bufA, W_hh0, W_ih1, W_hh1,
                                       b_ih1, b_hh1, W1, b1, bufB);
    // out = z W2^T + b2
    w2_kernel<<<1024, 128>>>(bufB, W2, b2, out, NROWS);
}

// round 17
// speedup vs baseline: 1.1726x; 1.0041x over previous
#include <cuda_runtime.h>

#define B_  256
#define T_  2048
#define H_  64
#define O_  2
#define NROWS (B_ * T_)
#define PF  4   // fused-scan xin prefetch depth (T_ % PF == 0)

// Scratch (device globals — no allocation allowed in kernel_launch)
__device__ float g_bufA[NROWS * H_];
__device__ float g_bufB[NROWS * H_];

// ---------- packed f32x2 helpers (sm_103a FFMA2 path) ----------
static __device__ __forceinline__ unsigned long long pack2(float lo, float hi) {
    unsigned long long r;
    asm("mov.b64 %0, {%1, %2};" : "=l"(r) : "f"(lo), "f"(hi));
    return r;
}
static __device__ __forceinline__ void unpack2(unsigned long long v, float& a, float& b) {
    asm("mov.b64 {%0, %1}, %2;" : "=f"(a), "=f"(b) : "l"(v));
}
static __device__ __forceinline__ unsigned long long fma2(unsigned long long a,
                                                          unsigned long long b,
                                                          unsigned long long c) {
    unsigned long long d;
    asm("fma.rn.f32x2 %0, %1, %2, %3;" : "=l"(d) : "l"(a), "l"(b), "l"(c));
    return d;
}
static __device__ __forceinline__ unsigned long long add2(unsigned long long a,
                                                          unsigned long long b) {
    unsigned long long d;
    asm("add.rn.f32x2 %0, %1, %2;" : "=l"(d) : "l"(a), "l"(b));
    return d;
}

// Fast tanh, rel err ~1e-7, saturates correctly.
static __device__ __forceinline__ float fast_tanh(float x) {
    float e = __expf(2.0f * x);
    return 1.0f - __fdividef(2.0f, e + 1.0f);
}

#define NAMED_BAR(id, cnt) asm volatile("bar.sync %0, %1;" :: "r"(id), "r"(cnt) : "memory")

// ============================================================================
// gemm64 (R12 full-row, 4 rows/iter — measured 139 us, at its plateau):
// out[r][j] = sum_k in[r][k]*W[j][k] + ba[j] + bb[j]
// ============================================================================
__global__ void __launch_bounds__(128) gemm64_kernel(
    const float* __restrict__ in, const float* __restrict__ W,
    const float* __restrict__ ba, const float* __restrict__ bb,
    float* __restrict__ out, int nrows)
{
    __shared__ __align__(16) unsigned long long xsm[4][2][4][32]; // [warp][buf][row][pair]
    const int l   = threadIdx.x & 31;
    const int wrp = threadIdx.x >> 5;
    const unsigned long long* Wu = (const unsigned long long*)W;
    const unsigned long long* Iu = (const unsigned long long*)in;

    unsigned long long wl[32], wh[32];
#pragma unroll
    for (int k = 0; k < 32; k++) {
        wl[k] = Wu[l * 32 + k];
        wh[k] = Wu[(l + 32) * 32 + k];
    }
    const float biasl = ba[l] + bb[l];
    const float biash = ba[l + 32] + bb[l + 32];

    const int  warpId = blockIdx.x * 4 + wrp;
    const int  nw     = gridDim.x * 4;
    const long stride = 4L * nw;

    long r = 4L * warpId;
    if (r >= nrows) return;
    unsigned long long xv[4];
#pragma unroll
    for (int q = 0; q < 4; q++)
        xv[q] = (r + q < nrows) ? Iu[(r + q) * 32 + l] : 0ull;
    int buf = 0;

    while (r < nrows) {
#pragma unroll
        for (int q = 0; q < 4; q++) xsm[wrp][buf][q][l] = xv[q];
        __syncwarp();

        long rn = r + stride;
        if (rn < nrows) {
#pragma unroll
            for (int q = 0; q < 4; q++)
                xv[q] = (rn + q < nrows) ? Iu[(rn + q) * 32 + l] : 0ull;
        }

        unsigned long long aL[4], aH[4], bL[4], bH[4];
#pragma unroll
        for (int q = 0; q < 4; q++) {
            aL[q] = pack2(biasl, 0.f); bL[q] = 0ull;
            aH[q] = pack2(biash, 0.f); bH[q] = 0ull;
        }
#pragma unroll
        for (int k = 0; k < 32; k += 2) {
#pragma unroll
            for (int q = 0; q < 4; q++) {
                ulonglong2 v = ((const ulonglong2*)&xsm[wrp][buf][q][0])[k >> 1];
                aL[q] = fma2(wl[k],     v.x, aL[q]);
                bL[q] = fma2(wl[k + 1], v.y, bL[q]);
                aH[q] = fma2(wh[k],     v.x, aH[q]);
                bH[q] = fma2(wh[k + 1], v.y, bH[q]);
            }
        }
#pragma unroll
        for (int q = 0; q < 4; q++) {
            if (r + q < nrows) {
                float s0, s1, t0, t1;
                unpack2(add2(aL[q], bL[q]), s0, s1);
                unpack2(add2(aH[q], bH[q]), t0, t1);
                out[(r + q) * 64 + l]      = s0 + s1;
                out[(r + q) * 64 + 32 + l] = t0 + t1;
            }
        }

        buf ^= 1;
        r = rn;
    }
}

// ============================================================================
// fused_scan + MLP-W1 (R12 config — measured ~745 us, at its plateau):
//   h0_i     = tanh(xin0_i + W_hh0 h0_{i-1})
//   h1_{i-1} = tanh(W_ih1 h0_{i-1} + b1rnn + W_hh1 h1_{i-2})
//   z_{i-2}  = relu(W1 h1_{i-2} + b1mlp)       <- reuses the h1_{i-2} loads
// Block = 256 thr = 2 batches x 4 warps; per-batch named barrier.
// Lane owns output j = wq*16+(l&15), K-half kh=l>>4; halves via shfl_xor(16).
// ============================================================================
__global__ void __launch_bounds__(256) fused_scan_kernel(
    const float* __restrict__ xin0,
    const float* __restrict__ Whh0, const float* __restrict__ Wih1,
    const float* __restrict__ Whh1,
    const float* __restrict__ b_ih1, const float* __restrict__ b_hh1,
    const float* __restrict__ W1,   const float* __restrict__ b1,
    float* __restrict__ zout)
{
    __shared__ __align__(16) float h0sm[2][2][64];
    __shared__ __align__(16) float h1sm[2][2][64];
    const int l     = threadIdx.x & 31;
    const int wid   = threadIdx.x >> 5;
    const int bl    = wid >> 2;            // batch slot (0..1)
    const int wq    = wid & 3;             // warp-in-batch
    const int j     = wq * 16 + (l & 15);  // owned output
    const int kh    = l >> 4;              // K-half
    const bool lead = (l < 16);
    const long b    = blockIdx.x * 2 + bl;
    const int barid = bl + 1;

    const unsigned long long* W0u = (const unsigned long long*)Whh0;
    const unsigned long long* Wxu = (const unsigned long long*)Wih1;
    const unsigned long long* W1u = (const unsigned long long*)Whh1;
    const unsigned long long* Wmu = (const unsigned long long*)W1;
    unsigned long long w0[16], wx[16], w1[16], wm[16];
#pragma unroll
    for (int m = 0; m < 16; m++) {
        const int k = kh * 16 + m;
        w0[m] = W0u[j * 32 + k];
        wx[m] = Wxu[j * 32 + k];
        w1[m] = W1u[j * 32 + k];
        wm[m] = Wmu[j * 32 + k];
    }
    const float bias1g = lead ? (b_ih1[j] + b_hh1[j]) : 0.f;
    const float b1m    = lead ? b1[j] : 0.f;

    if (lead) {
        h0sm[bl][0][j] = 0.f;   // h0_{-1}
        h1sm[bl][0][j] = 0.f;   // h1_{-2}
    }

    const float* xb = xin0 + b * T_ * 64;
    float*       zb = zout + b * T_ * 64;

    float xs[PF];
#pragma unroll
    for (int s = 0; s < PF; s++) xs[s] = xb[s * 64 + j];

    NAMED_BAR(barid, 128);

    int p = 0;
    for (int tb = 0; tb < T_; tb += PF) {
#pragma unroll
        for (int u = 0; u < PF; u++) {
            const int i = tb + u;
            const float xv = lead ? xs[u] : 0.f;
            if (i + PF < T_) xs[u] = xb[(i + PF) * 64 + j];

            unsigned long long a0 = pack2(xv, 0.f), a1 = 0ull;       // Whh0.h0
            unsigned long long c0 = pack2(bias1g, 0.f), c1 = 0ull;   // Wih1.h0
            unsigned long long d0 = 0ull, d1 = 0ull;                 // Whh1.h1
            unsigned long long m0 = pack2(b1m, 0.f), m1 = 0ull;      // W1.h1
            const ulonglong2* hp0 = (const ulonglong2*)&h0sm[bl][p][kh * 32];
            const ulonglong2* hp1 = (const ulonglong2*)&h1sm[bl][p][kh * 32];
#pragma unroll
            for (int m = 0; m < 16; m += 2) {
                ulonglong2 v = hp0[m >> 1];   // h0_{i-1}: one load, two uses
                ulonglong2 g = hp1[m >> 1];   // h1_{i-2}: one load, two uses
                a0 = fma2(w0[m],     v.x, a0);
                a1 = fma2(w0[m + 1], v.y, a1);
                c0 = fma2(wx[m],     v.x, c0);
                c1 = fma2(wx[m + 1], v.y, c1);
                d0 = fma2(w1[m],     g.x, d0);
                d1 = fma2(w1[m + 1], g.y, d1);
                m0 = fma2(wm[m],     g.x, m0);
                m1 = fma2(wm[m + 1], g.y, m1);
            }
            float s0, s1, e0, e1, z0, z1;
            unpack2(add2(a0, a1), s0, s1);
            unpack2(add2(add2(c0, c1), add2(d0, d1)), e0, e1);
            unpack2(add2(m0, m1), z0, z1);
            float sh = s0 + s1;
            float eh = e0 + e1;
            float zh = z0 + z1;
            sh += __shfl_xor_sync(0xffffffffu, sh, 16);   // combine K-halves
            eh += __shfl_xor_sync(0xffffffffu, eh, 16);
            zh += __shfl_xor_sync(0xffffffffu, zh, 16);

            const float h0v = fast_tanh(sh);
            float h1v = fast_tanh(eh);          // = h1_{i-1}
            if (i == 0) h1v = 0.f;              // h1_{-1} := 0
            const float zv = fmaxf(zh, 0.f);    // = z_{i-2}

            if (lead) {
                h0sm[bl][p ^ 1][j] = h0v;
                h1sm[bl][p ^ 1][j] = h1v;
                if (i >= 2) zb[(i - 2) * 64 + j] = zv;
            }
            NAMED_BAR(barid, 128);
            p ^= 1;
        }
    }

    // Epilogue step 1: h1_{T-1} and z_{T-2}
    {
        unsigned long long c0 = pack2(bias1g, 0.f), c1 = 0ull;
        unsigned long long d0 = 0ull, d1 = 0ull;
        unsigned long long m0 = pack2(b1m, 0.f), m1 = 0ull;
        const ulonglong2* hp0 = (const ulonglong2*)&h0sm[bl][p][kh * 32];
        const ulonglong2* hp1 = (const ulonglong2*)&h1sm[bl][p][kh * 32];
#pragma unroll
        for (int m = 0; m < 16; m += 2) {
            ulonglong2 v = hp0[m >> 1];   // h0_{T-1}
            ulonglong2 g = hp1[m >> 1];   // h1_{T-2}
            c0 = fma2(wx[m],     v.x, c0);
            c1 = fma2(wx[m + 1], v.y, c1);
            d0 = fma2(w1[m],     g.x, d0);
            d1 = fma2(w1[m + 1], g.y, d1);
            m0 = fma2(wm[m],     g.x, m0);
            m1 = fma2(wm[m + 1], g.y, m1);
        }
        float e0, e1, z0, z1;
        unpack2(add2(add2(c0, c1), add2(d0, d1)), e0, e1);
        unpack2(add2(m0, m1), z0, z1);
        float eh = e0 + e1;
        float zh = z0 + z1;
        eh += __shfl_xor_sync(0xffffffffu, eh, 16);
        zh += __shfl_xor_sync(0xffffffffu, zh, 16);
        if (lead) {
            zb[(T_ - 2) * 64 + j] = fmaxf(zh, 0.f);
            h1sm[bl][p ^ 1][j] = fast_tanh(eh);   // h1_{T-1}
        }
        NAMED_BAR(barid, 128);
    }
    // Epilogue step 2: z_{T-1} = relu(W1 h1_{T-1} + b1)
    {
        unsigned long long m0 = pack2(b1m, 0.f), m1 = 0ull;
        const ulonglong2* hp1 = (const ulonglong2*)&h1sm[bl][p ^ 1][kh * 32];
#pragma unroll
        for (int m = 0; m < 16; m += 2) {
            ulonglong2 g = hp1[m >> 1];
            m0 = fma2(wm[m],     g.x, m0);
            m1 = fma2(wm[m + 1], g.y, m1);
        }
        float z0, z1;
        unpack2(add2(m0, m1), z0, z1);
        float zh = z0 + z1;
        zh += __shfl_xor_sync(0xffffffffu, zh, 16);
        if (lead) zb[(T_ - 1) * 64 + j] = fmaxf(zh, 0.f);
    }
}

// ============================================================================
// w2: out[r][o] = sum_j W2[o][j] z[r][j] + b2[o]  (O=2). 16 rows/iter:
// 4 KB of DRAM reads in flight per warp (2x the 8-row version's 50% DRAM).
// ============================================================================
__global__ void __launch_bounds__(128) w2_kernel(
    const float* __restrict__ z, const float* __restrict__ W2,
    const float* __restrict__ b2, float* __restrict__ out, int nrows)
{
    const int l = threadIdx.x & 31;
    const int wrp = threadIdx.x >> 5;
    const unsigned long long* Zu  = (const unsigned long long*)z;
    const unsigned long long* W2u = (const unsigned long long*)W2;

    const unsigned long long w2a = W2u[l];        // (W2[0][2l], W2[0][2l+1])
    const unsigned long long w2b = W2u[32 + l];   // (W2[1][2l], W2[1][2l+1])
    const float b20 = b2[0], b21 = b2[1];

    const int  warpId = blockIdx.x * 4 + wrp;
    const int  nw     = gridDim.x * 4;
    const long stride = 16L * nw;

    for (long r = 16L * warpId; r < nrows; r += stride) {
        unsigned long long zv[16];
#pragma unroll
        for (int q = 0; q < 16; q++)
            zv[q] = (r + q < nrows) ? Zu[(r + q) * 32 + l] : 0ull;

        float p0[16], p1[16];
#pragma unroll
        for (int q = 0; q < 16; q++) {
            float a0, a1, c0, c1;
            unpack2(fma2(w2a, zv[q], 0ull), a0, a1);
            unpack2(fma2(w2b, zv[q], 0ull), c0, c1);
            p0[q] = a0 + a1;
            p1[q] = c0 + c1;
        }
#pragma unroll
        for (int off = 16; off; off >>= 1) {
#pragma unroll
            for (int q = 0; q < 16; q++) {
                p0[q] += __shfl_xor_sync(0xffffffffu, p0[q], off);
                p1[q] += __shfl_xor_sync(0xffffffffu, p1[q], off);
            }
        }
        if (l == 0) {
#pragma unroll
            for (int q = 0; q < 16; q++)
                if (r + q < nrows)
                    *reinterpret_cast<float2*>(&out[(r + q) * 2]) =
                        make_float2(p0[q] + b20, p1[q] + b21);
        }
    }
}

// ============================================================================
extern "C" void kernel_launch(void* const* d_in, const int* in_sizes, int n_in,
                              void* d_out, int out_size)
{
    const float* x     = (const float*)d_in[0];
    const float* W_ih0 = (const float*)d_in[1];
    const float* W_hh0 = (const float*)d_in[2];
    const float* b_ih0 = (const float*)d_in[3];
    const float* b_hh0 = (const float*)d_in[4];
    const float* W_ih1 = (const float*)d_in[5];
    const float* W_hh1 = (const float*)d_in[6];
    const float* b_ih1 = (const float*)d_in[7];
    const float* b_hh1 = (const float*)d_in[8];
    const float* W1    = (const float*)d_in[9];
    const float* b1    = (const float*)d_in[10];
    const float* W2    = (const float*)d_in[11];
    const float* b2    = (const float*)d_in[12];
    float* out = (float*)d_out;

    static float* bufA = nullptr;
    static float* bufB = nullptr;
    if (!bufA) {
        cudaGetSymbolAddress((void**)&bufA, g_bufA);
        cudaGetSymbolAddress((void**)&bufB, g_bufB);
    }

    // xin0 = x W_ih0^T + b_ih0 + b_hh0
    gemm64_kernel<<<1184, 128>>>(x, W_ih0, b_ih0, b_hh0, bufA, NROWS);
    // both RNN layers + MLP W1 -> z
    fused_scan_kernel<<<B_ / 2, 256>>>(bufA, W_hh0, W_ih1, W_hh1,
                                       b_ih1, b_hh1, W1, b1, bufB);
    // out = z W2^T + b2
    w2_kernel<<<1024, 128>>>(bufB, W2, b2, out, NROWS);
}